// round 1
// baseline (speedup 1.0000x reference)
#include <cuda_runtime.h>
#include <cuda_bf16.h>
#include <cstddef>

// ---------------- problem constants ----------------
#define NB 8
#define NC 32
#define C4 128          // NC*4 channels into/out of each conv
#define KSZ 1152        // C4 * 9 (GEMM K)
// level sizes
#define H1 112
#define H2 56
#define H3 28

// ---------------- scratch (static device globals; no allocation) ----------------
__device__ float g_sub1[(size_t)NB * C4 * H1 * H1];
__device__ float g_y1  [(size_t)NB * C4 * H1 * H1];
__device__ float g_sub2[(size_t)NB * C4 * H2 * H2];
__device__ float g_y2  [(size_t)NB * C4 * H2 * H2];
__device__ float g_sub3[(size_t)NB * C4 * H3 * H3];
__device__ float g_y3  [(size_t)NB * C4 * H3 * H3];
__device__ float g_r2  [(size_t)NB * NC * H2 * H2];
__device__ float g_r1  [(size_t)NB * NC * H1 * H1];
__device__ float g_wT  [(size_t)KSZ * C4];

// ---------------- weight transpose: OIHW -> [k = tap*128 + ic][n] ----------------
__global__ void wt_transpose(const float* __restrict__ w, float* __restrict__ wT) {
    int idx = blockIdx.x * 256 + threadIdx.x;
    if (idx >= KSZ * C4) return;
    int n   = idx & 127;
    int k   = idx >> 7;
    int tap = k >> 7;       // 0..8 (kh*3+kw)
    int ic  = k & 127;
    wT[idx] = w[(size_t)n * KSZ + ic * 9 + tap];
}

// ---------------- Haar DWT: src (strided LL view) -> dst [B, C*4(sub), h, w] ----------------
__global__ void dwt_k(const float* __restrict__ src, float* __restrict__ dst,
                      int hOut, int wOut, long cstride, long bstride) {
    long total = (long)NB * NC * hOut * wOut;
    long idx = (long)blockIdx.x * blockDim.x + threadIdx.x;
    if (idx >= total) return;
    int wIn = wOut * 2;
    int j = (int)(idx % wOut);
    long t = idx / wOut;
    int i = (int)(t % hOut); t /= hOut;
    int c = (int)(t % NC);
    int b = (int)(t / NC);

    const float* s = src + (long)b * bstride + (long)c * cstride + (long)(2 * i) * wIn + 2 * j;
    float a  = s[0];
    float bb = s[1];
    float cc = s[wIn];
    float dd = s[wIn + 1];
    long hw = (long)hOut * wOut;
    float* d = dst + ((long)(b * NC + c) * 4) * hw + (long)i * wOut + j;
    d[0]      = (a + bb + cc + dd) * 0.5f;
    d[hw]     = (a - bb + cc - dd) * 0.5f;
    d[2 * hw] = (a + bb - cc - dd) * 0.5f;
    d[3 * hw] = (a - bb - cc + dd) * 0.5f;
}

// ---------------- Haar IDWT: y [B, C*4, h, w] (+ optional ll from prev level) -> out [B, C, 2h, 2w] ----------------
__global__ void idwt_k(const float* __restrict__ y, const float* __restrict__ addll,
                       float* __restrict__ out, int h, int w, const float* __restrict__ bias) {
    long total = (long)NB * NC * h * w;
    long idx = (long)blockIdx.x * blockDim.x + threadIdx.x;
    if (idx >= total) return;
    int j = (int)(idx % w);
    long t = idx / w;
    int i = (int)(t % h); t /= h;
    int c = (int)(t % NC);
    int b = (int)(t / NC);

    long hw = (long)h * w;
    const float* yp = y + ((long)(b * NC + c) * 4) * hw + (long)i * w + j;
    float ll = yp[0];
    if (addll) ll += addll[(long)(b * NC + c) * hw + (long)i * w + j];
    float lh = yp[hw];
    float hl = yp[2 * hw];
    float hh = yp[3 * hw];
    float a  = (ll + lh + hl + hh) * 0.5f;
    float bb = (ll - lh + hl - hh) * 0.5f;
    float cc = (ll + lh - hl - hh) * 0.5f;
    float dd = (ll - lh - hl + hh) * 0.5f;
    float bv = bias ? bias[c] : 0.0f;
    int W2 = 2 * w;
    float* o = out + (long)(b * NC + c) * (4 * hw) + (long)(2 * i) * W2 + 2 * j;
    o[0]      = a  + bv;
    o[1]      = bb + bv;
    o[W2]     = cc + bv;
    o[W2 + 1] = dd + bv;
}

// ---------------- implicit-GEMM direct conv (fp32, 3x3, pad 1, stride 1) ----------------
// GEMM: out[m, n] = sum_k A[m,k] * wT[k,n];  m = spatial within one batch image,
// n = output channel (128 = BN -> one block covers all N), k = tap*128 + ic.
#define BM 128
#define BN 128
#define BK 16

__global__ __launch_bounds__(256, 2)
void conv_igemm(const float* __restrict__ in, const float* __restrict__ wT,
                float* __restrict__ out, int h, int w) {
    const int hw = h * w;
    const int b  = blockIdx.y;
    const int m0 = blockIdx.x * BM;
    const float* inb  = in  + (size_t)b * C4 * hw;
    float*       outb = out + (size_t)b * C4 * hw;

    __shared__ float As[BK][BM + 4];
    __shared__ float Bs[BK][BN];

    const int tid   = threadIdx.x;
    const int a_row = tid & 31;   // m row within tile (+32*i)
    const int a_kc  = tid >> 5;   // k col (0..7, second = +8)

    int  oh[4], ow[4];
    bool inimg[4];
#pragma unroll
    for (int i = 0; i < 4; i++) {
        int msp = m0 + a_row + 32 * i;
        inimg[i] = msp < hw;
        oh[i] = msp / w;
        ow[i] = msp - oh[i] * w;
    }
    const int b_kr = tid >> 5;
    const int b_n  = (tid & 31) * 4;

    const int lane = tid & 31;
    const int warp = tid >> 5;
    const int tm = (warp & 1) * 64 + (lane & 7) * 8;   // 2 warps tile M (64 each)
    const int tn = (warp >> 1) * 32 + (lane >> 3) * 8; // 4 warps tile N (32 each)

    float acc[8][8];
#pragma unroll
    for (int i = 0; i < 8; i++)
#pragma unroll
        for (int j = 0; j < 8; j++) acc[i][j] = 0.0f;

    for (int k0 = 0; k0 < KSZ; k0 += BK) {
        int tap = k0 >> 7;          // constant within chunk (16 | 128)
        int icb = k0 & 127;
        int kh  = tap / 3 - 1;
        int kw  = tap - (tap / 3) * 3 - 1;

        // ---- A tile: input patches, coalesced along m ----
#pragma unroll
        for (int i = 0; i < 4; i++) {
            int ih = oh[i] + kh;
            int iw = ow[i] + kw;
            bool v = inimg[i] && ((unsigned)ih < (unsigned)h) && ((unsigned)iw < (unsigned)w);
            const float* p = inb + (size_t)(icb + a_kc) * hw + (long)ih * w + iw;
            float v0 = v ? p[0] : 0.0f;
            float v1 = v ? p[(size_t)8 * hw] : 0.0f;
            As[a_kc][a_row + 32 * i]     = v0;
            As[a_kc + 8][a_row + 32 * i] = v1;
        }
        // ---- B tile: transposed weights, vectorized ----
        {
            *(float4*)&Bs[b_kr][b_n]     = *(const float4*)&wT[(size_t)(k0 + b_kr) * C4 + b_n];
            *(float4*)&Bs[b_kr + 8][b_n] = *(const float4*)&wT[(size_t)(k0 + b_kr + 8) * C4 + b_n];
        }
        __syncthreads();

#pragma unroll
        for (int kk = 0; kk < BK; kk++) {
            float af[8], bf[8];
            *(float4*)&af[0] = *(const float4*)&As[kk][tm];
            *(float4*)&af[4] = *(const float4*)&As[kk][tm + 4];
            *(float4*)&bf[0] = *(const float4*)&Bs[kk][tn];
            *(float4*)&bf[4] = *(const float4*)&Bs[kk][tn + 4];
#pragma unroll
            for (int i = 0; i < 8; i++)
#pragma unroll
                for (int j = 0; j < 8; j++)
                    acc[i][j] = fmaf(af[i], bf[j], acc[i][j]);
        }
        __syncthreads();
    }

    // ---- store: thread's 8 m are consecutive spatial addresses ----
    int ms = m0 + tm;
    if (ms < hw) {
#pragma unroll
        for (int j = 0; j < 8; j++) {
            float* o = outb + (size_t)(tn + j) * hw + ms;
            *(float4*)&o[0] = make_float4(acc[0][j], acc[1][j], acc[2][j], acc[3][j]);
            *(float4*)&o[4] = make_float4(acc[4][j], acc[5][j], acc[6][j], acc[7][j]);
        }
    }
}

// ---------------- launch ----------------
static inline int ceil_div(long a, int b) { return (int)((a + b - 1) / b); }

extern "C" void kernel_launch(void* const* d_in, const int* in_sizes, int n_in,
                              void* d_out, int out_size) {
    const float* x    = (const float*)d_in[0];
    const float* wgt  = (const float*)d_in[1];
    const float* bias = (const float*)d_in[2];
    float* out = (float*)d_out;

    float *sub1, *y1, *sub2, *y2, *sub3, *y3, *r2, *r1, *wT;
    cudaGetSymbolAddress((void**)&sub1, g_sub1);
    cudaGetSymbolAddress((void**)&y1,   g_y1);
    cudaGetSymbolAddress((void**)&sub2, g_sub2);
    cudaGetSymbolAddress((void**)&y2,   g_y2);
    cudaGetSymbolAddress((void**)&sub3, g_sub3);
    cudaGetSymbolAddress((void**)&y3,   g_y3);
    cudaGetSymbolAddress((void**)&r2,   g_r2);
    cudaGetSymbolAddress((void**)&r1,   g_r1);
    cudaGetSymbolAddress((void**)&wT,   g_wT);

    // weight transpose (tiny)
    wt_transpose<<<ceil_div((long)KSZ * C4, 256), 256>>>(wgt, wT);

    const long HW0 = 224L * 224;
    const long HW1 = (long)H1 * H1;
    const long HW2 = (long)H2 * H2;

    // level 1: dwt(x) -> sub1; conv -> y1
    dwt_k<<<ceil_div((long)NB * NC * H1 * H1, 256), 256>>>(x, sub1, H1, H1, HW0, (long)NC * HW0);
    conv_igemm<<<dim3(ceil_div(HW1, BM), NB), 256>>>(sub1, wT, y1, H1, H1);

    // level 2: dwt(LL of sub1) -> sub2; conv -> y2
    dwt_k<<<ceil_div((long)NB * NC * H2 * H2, 256), 256>>>(sub1, sub2, H2, H2, 4 * HW1, (long)C4 * HW1);
    conv_igemm<<<dim3(ceil_div(HW2, BM), NB), 256>>>(sub2, wT, y2, H2, H2);

    // level 3: dwt(LL of sub2) -> sub3; conv -> y3
    dwt_k<<<ceil_div((long)NB * NC * H3 * H3, 256), 256>>>(sub2, sub3, H3, H3, 4 * HW2, (long)C4 * HW2);
    conv_igemm<<<dim3(ceil_div((long)H3 * H3, BM), NB), 256>>>(sub3, wT, y3, H3, H3);

    // reconstruction
    idwt_k<<<ceil_div((long)NB * NC * H3 * H3, 256), 256>>>(y3, nullptr, r2, H3, H3, nullptr);
    idwt_k<<<ceil_div((long)NB * NC * H2 * H2, 256), 256>>>(y2, r2, r1, H2, H2, nullptr);
    idwt_k<<<ceil_div((long)NB * NC * H1 * H1, 256), 256>>>(y1, r1, out, H1, H1, bias);
}

// round 3
// speedup vs baseline: 1.5806x; 1.5806x over previous
#include <cuda_runtime.h>
#include <cuda_bf16.h>
#include <cstdint>
#include <cstddef>

// ================= problem constants =================
#define NB 8
#define NC 32
#define C4 128
#define H1 112
#define H2 56
#define H3 28

#define BM 128
#define BK 64
#define NSTAGE 27            // 9 taps x 3 products
#define NCHUNK (NSTAGE * 2)  // BK=64, 128 ic per stage

// smem: bufA0 16K | bufB0 16K | bufA1 16K | bufB1 16K
#define BUF_BYTES 32768
#define SMEM_TOTAL (2 * BUF_BYTES)

// ================= scratch =================
__device__ __nv_bfloat16 g_aHi1[(size_t)NB * H1 * H1 * C4];
__device__ __nv_bfloat16 g_aLo1[(size_t)NB * H1 * H1 * C4];
__device__ __nv_bfloat16 g_aHi2[(size_t)NB * H2 * H2 * C4];
__device__ __nv_bfloat16 g_aLo2[(size_t)NB * H2 * H2 * C4];
__device__ __nv_bfloat16 g_aHi3[(size_t)NB * H3 * H3 * C4];
__device__ __nv_bfloat16 g_aLo3[(size_t)NB * H3 * H3 * C4];
__device__ float g_ll1[(size_t)NB * H1 * H1 * NC];
__device__ float g_ll2[(size_t)NB * H2 * H2 * NC];
__device__ float g_y1 [(size_t)NB * H1 * H1 * C4];
__device__ float g_y2 [(size_t)NB * H2 * H2 * C4];
__device__ float g_y3 [(size_t)NB * H3 * H3 * C4];
__device__ float g_r2 [(size_t)NB * H2 * H2 * NC];
__device__ float g_r1 [(size_t)NB * H1 * H1 * NC];
__device__ __nv_bfloat16 g_wHi[(size_t)9 * C4 * C4];   // [tap][n][ic]
__device__ __nv_bfloat16 g_wLo[(size_t)9 * C4 * C4];

// ================= helpers =================
__device__ __forceinline__ uint32_t smem_u32(const void* p) {
    uint32_t a;
    asm("{ .reg .u64 t; cvta.to.shared.u64 t, %1; cvt.u32.u64 %0, t; }" : "=r"(a) : "l"(p));
    return a;
}
__device__ __forceinline__ void ldsm_x4(uint32_t& r0, uint32_t& r1, uint32_t& r2, uint32_t& r3,
                                        uint32_t addr) {
    asm volatile("ldmatrix.sync.aligned.m8n8.x4.shared.b16 {%0,%1,%2,%3}, [%4];"
                 : "=r"(r0), "=r"(r1), "=r"(r2), "=r"(r3) : "r"(addr));
}
__device__ __forceinline__ void mma16816(float* c, const uint32_t* a, const uint32_t* b) {
    asm volatile(
        "mma.sync.aligned.m16n8k16.row.col.f32.bf16.bf16.f32 "
        "{%0,%1,%2,%3}, {%4,%5,%6,%7}, {%8,%9}, {%0,%1,%2,%3};"
        : "+f"(c[0]), "+f"(c[1]), "+f"(c[2]), "+f"(c[3])
        : "r"(a[0]), "r"(a[1]), "r"(a[2]), "r"(a[3]), "r"(b[0]), "r"(b[1]));
}
__device__ __forceinline__ void sts128(uint32_t addr, uint4 v) {
    asm volatile("st.shared.v4.b32 [%0], {%1,%2,%3,%4};"
                 :: "r"(addr), "r"(v.x), "r"(v.y), "r"(v.z), "r"(v.w) : "memory");
}

// ================= weight split: OIHW fp32 -> [tap][o][ic] bf16 hi/lo =================
__global__ void wsplit_k(const float* __restrict__ w,
                         __nv_bfloat16* __restrict__ wHi, __nv_bfloat16* __restrict__ wLo) {
    int idx = blockIdx.x * 256 + threadIdx.x;
    if (idx >= 9 * C4 * C4) return;
    int tap = idx / (C4 * C4);
    int rem = idx - tap * C4 * C4;
    int o = rem >> 7, ic = rem & 127;
    float v = w[((size_t)o * C4 + ic) * 9 + tap];
    __nv_bfloat16 hi = __float2bfloat16(v);
    wHi[idx] = hi;
    wLo[idx] = __float2bfloat16(v - __bfloat162float(hi));
}

// ================= DWT =================
__global__ void dwt_k(const float* __restrict__ src, int srcNCHW, int wIn,
                      __nv_bfloat16* __restrict__ oHi, __nv_bfloat16* __restrict__ oLo,
                      float* __restrict__ oLL, int h, int w) {
    long total = (long)NB * h * w * NC;
    long idx = (long)blockIdx.x * 256 + threadIdx.x;
    if (idx >= total) return;
    int c = (int)(idx & 31);
    long t = idx >> 5;
    int j = (int)(t % w); t /= w;
    int i = (int)(t % h);
    int b = (int)(t / h);

    float a, bb, cc, dd;
    if (srcNCHW) {
        const float* s = src + (((size_t)(b * NC + c)) * (2 * h) + 2 * i) * (size_t)wIn + 2 * j;
        a = s[0]; bb = s[1]; cc = s[wIn]; dd = s[wIn + 1];
    } else {
        const float* s = src + (((size_t)b * (2 * h) + 2 * i) * (size_t)wIn + 2 * j) * NC + c;
        a = s[0]; bb = s[NC]; cc = s[(size_t)wIn * NC]; dd = s[(size_t)wIn * NC + NC];
    }
    float ll = (a + bb + cc + dd) * 0.5f;
    float lh = (a - bb + cc - dd) * 0.5f;
    float hl = (a + bb - cc - dd) * 0.5f;
    float hh = (a - bb - cc + dd) * 0.5f;

    size_t pos = (size_t)(b * h + i) * w + j;
    size_t obase = pos * C4 + c * 4;
    __nv_bfloat16 h0 = __float2bfloat16(ll), h1 = __float2bfloat16(lh);
    __nv_bfloat16 h2 = __float2bfloat16(hl), h3 = __float2bfloat16(hh);
    __nv_bfloat162 hp0(h0, h1), hp1(h2, h3);
    __nv_bfloat162 lp0(__float2bfloat16(ll - __bfloat162float(h0)),
                       __float2bfloat16(lh - __bfloat162float(h1)));
    __nv_bfloat162 lp1(__float2bfloat16(hl - __bfloat162float(h2)),
                       __float2bfloat16(hh - __bfloat162float(h3)));
    uint2 hv, lv;
    hv.x = *(uint32_t*)&hp0; hv.y = *(uint32_t*)&hp1;
    lv.x = *(uint32_t*)&lp0; lv.y = *(uint32_t*)&lp1;
    *(uint2*)(oHi + obase) = hv;
    *(uint2*)(oLo + obase) = lv;
    if (oLL) oLL[pos * NC + c] = ll;
}

// ================= IDWT =================
__global__ void idwt_k(const float* __restrict__ y, const float* __restrict__ addll,
                       float* __restrict__ out, int h, int w, int finalOut,
                       const float* __restrict__ bias) {
    long total = (long)NB * h * w * NC;
    long idx = (long)blockIdx.x * 256 + threadIdx.x;
    if (idx >= total) return;
    int c = (int)(idx & 31);
    long t = idx >> 5;
    int j = (int)(t % w); t /= w;
    int i = (int)(t % h);
    int b = (int)(t / h);

    size_t pos = (size_t)(b * h + i) * w + j;
    float4 s = *(const float4*)(y + pos * C4 + c * 4);
    float ll = s.x, lh = s.y, hl = s.z, hh = s.w;
    if (addll) ll += addll[pos * NC + c];
    float a  = (ll + lh + hl + hh) * 0.5f;
    float bb = (ll - lh + hl - hh) * 0.5f;
    float cc = (ll + lh - hl - hh) * 0.5f;
    float dd = (ll - lh - hl + hh) * 0.5f;

    int H = 2 * h, W = 2 * w;
    if (finalOut) {
        float bv = bias[c];
        float* o = out + (((size_t)(b * NC + c)) * H + 2 * i) * (size_t)W + 2 * j;
        o[0] = a + bv; o[1] = bb + bv;
        o[W] = cc + bv; o[W + 1] = dd + bv;
    } else {
        float* o = out + (((size_t)b * H + 2 * i) * (size_t)W + 2 * j) * NC + c;
        o[0] = a; o[NC] = bb;
        o[(size_t)W * NC] = cc; o[(size_t)W * NC + NC] = dd;
    }
}

// ================= conv via mma.sync bf16 (3-product split) =================
// GEMM: y[m, n] = sum over 27 stages (tap,p) of A_sel[m, ic+shift(tap)] * W_sel[tap][n][ic]
// m = b*hw + pos (global). M is a multiple of 128 at every level.
__global__ __launch_bounds__(256, 2)
void conv_mma(const __nv_bfloat16* __restrict__ aHi, const __nv_bfloat16* __restrict__ aLo,
              const __nv_bfloat16* __restrict__ wHi, const __nv_bfloat16* __restrict__ wLo,
              float* __restrict__ y, int h, int w) {
    extern __shared__ __align__(128) char smem[];
    const uint32_t sb = smem_u32(smem);
    const int hw = h * w;
    const int tid = threadIdx.x;
    const int lane = tid & 31;
    const int wid = tid >> 5;
    const int wm = wid & 1;        // 2 warps along M (64 rows each)
    const int wn = wid >> 1;       // 4 warps along N (32 cols each)
    const int m0 = blockIdx.x * BM;

    // ---- per-thread loader geometry (row = tid>>1, half = tid&1) ----
    const int lr   = tid >> 1;
    const int half = tid & 1;
    const int mg  = m0 + lr;
    const int b   = mg / hw;
    const int pos = mg - b * hw;
    const int oh = pos / w;
    const int ow = pos - oh * w;
    const size_t aRowBase = (size_t)b * hw * C4 + (size_t)half * 32;   // + ihw*C4 later
    const uint32_t stRow = (uint32_t)lr * 128;                         // smem row byte offset
    const int rx = lr & 7;                                             // swizzle key

    // ---- ldmatrix addresses (per warp lane), row-dependent parts precomputed ----
    uint32_t aRowOff[4]; int aSx[4];
#pragma unroll
    for (int mt = 0; mt < 4; mt++) {
        int rowA = wm * 64 + mt * 16 + (lane & 15);
        aRowOff[mt] = (uint32_t)rowA * 128;
        aSx[mt] = rowA & 7;
    }
    const int aSegBase = lane >> 4;              // 0/1 : k-halves of k16
    uint32_t bRowOff[2]; int bSx[2];
#pragma unroll
    for (int bt = 0; bt < 2; bt++) {
        int rowB = wn * 32 + bt * 16 + (lane & 7) + ((lane & 16) >> 1);
        bRowOff[bt] = (uint32_t)rowB * 128;
        bSx[bt] = rowB & 7;
    }
    const int bSegBase = (lane >> 3) & 1;

    float acc[4][4][4];
#pragma unroll
    for (int i = 0; i < 4; i++)
#pragma unroll
        for (int j = 0; j < 4; j++)
#pragma unroll
            for (int q = 0; q < 4; q++) acc[i][j][q] = 0.0f;

    // chunk loader (issued as a lambda-style macro body)
    auto load_chunk = [&](int ch) {
        const int stage = ch >> 1;
        const int kc    = ch & 1;
        const int tap   = stage / 3;
        const int p     = stage - tap * 3;
        const int kh = tap / 3 - 1;
        const int kw = tap - (tap / 3) * 3 - 1;
        const uint32_t buf = sb + (uint32_t)(ch & 1) * BUF_BYTES;

        // A: 128 rows x 64 ic
        {
            const __nv_bfloat16* aSrc = (p == 1) ? aLo : aHi;
            int ih = oh + kh, iw = ow + kw;
            bool v = ((unsigned)ih < (unsigned)h) && ((unsigned)iw < (unsigned)w);
            const uint4* pa = (const uint4*)(aSrc + aRowBase + ((size_t)ih * w + iw) * C4 + kc * 64);
            uint4 v0 = make_uint4(0,0,0,0), v1 = v0, v2 = v0, v3 = v0;
            if (v) { v0 = pa[0]; v1 = pa[1]; v2 = pa[2]; v3 = pa[3]; }
            int s0 = half * 4;
            sts128(buf + stRow + (uint32_t)((s0 + 0) ^ rx) * 16, v0);
            sts128(buf + stRow + (uint32_t)((s0 + 1) ^ rx) * 16, v1);
            sts128(buf + stRow + (uint32_t)((s0 + 2) ^ rx) * 16, v2);
            sts128(buf + stRow + (uint32_t)((s0 + 3) ^ rx) * 16, v3);
        }
        // B: 128 n-rows x 64 ic
        {
            const __nv_bfloat16* wSrc = (p == 2) ? wLo : wHi;
            const uint4* pb = (const uint4*)(wSrc + ((size_t)tap * C4 + lr) * C4 + kc * 64 + half * 32);
            uint4 v0 = pb[0], v1 = pb[1], v2 = pb[2], v3 = pb[3];
            int s0 = half * 4;
            uint32_t bbuf = buf + 16384;
            sts128(bbuf + stRow + (uint32_t)((s0 + 0) ^ rx) * 16, v0);
            sts128(bbuf + stRow + (uint32_t)((s0 + 1) ^ rx) * 16, v1);
            sts128(bbuf + stRow + (uint32_t)((s0 + 2) ^ rx) * 16, v2);
            sts128(bbuf + stRow + (uint32_t)((s0 + 3) ^ rx) * 16, v3);
        }
    };

    load_chunk(0);

    for (int ch = 0; ch < NCHUNK; ch++) {
        __syncthreads();
        if (ch + 1 < NCHUNK) load_chunk(ch + 1);

        const uint32_t bufA = sb + (uint32_t)(ch & 1) * BUF_BYTES;
        const uint32_t bufB = bufA + 16384;

#pragma unroll
        for (int ks = 0; ks < 4; ks++) {
            uint32_t af[4][4];
#pragma unroll
            for (int mt = 0; mt < 4; mt++) {
                int seg = ks * 2 + aSegBase;
                ldsm_x4(af[mt][0], af[mt][1], af[mt][2], af[mt][3],
                        bufA + aRowOff[mt] + (uint32_t)(seg ^ aSx[mt]) * 16);
            }
            uint32_t bf[4][2];
#pragma unroll
            for (int bt = 0; bt < 2; bt++) {
                int seg = ks * 2 + bSegBase;
                uint32_t r0, r1, r2, r3;
                ldsm_x4(r0, r1, r2, r3,
                        bufB + bRowOff[bt] + (uint32_t)(seg ^ bSx[bt]) * 16);
                bf[bt * 2 + 0][0] = r0; bf[bt * 2 + 0][1] = r1;
                bf[bt * 2 + 1][0] = r2; bf[bt * 2 + 1][1] = r3;
            }
#pragma unroll
            for (int mt = 0; mt < 4; mt++)
#pragma unroll
                for (int nt = 0; nt < 4; nt++)
                    mma16816(acc[mt][nt], af[mt], bf[nt]);
        }
    }

    // ---- epilogue: write y NHWC fp32 ----
    const int mBase = m0 + wm * 64 + (lane >> 2);
    const int nBase = wn * 32 + (lane & 3) * 2;
#pragma unroll
    for (int mt = 0; mt < 4; mt++) {
        int m = mBase + mt * 16;
        float* d0 = y + (size_t)m * C4 + nBase;
        float* d1 = d0 + 8 * C4;
#pragma unroll
        for (int nt = 0; nt < 4; nt++) {
            *(float2*)(d0 + nt * 8) = make_float2(acc[mt][nt][0], acc[mt][nt][1]);
            *(float2*)(d1 + nt * 8) = make_float2(acc[mt][nt][2], acc[mt][nt][3]);
        }
    }
}

// ================= launch =================
static inline int cdiv(long a, int b) { return (int)((a + b - 1) / b); }

extern "C" void kernel_launch(void* const* d_in, const int* in_sizes, int n_in,
                              void* d_out, int out_size) {
    const float* x    = (const float*)d_in[0];
    const float* wgt  = (const float*)d_in[1];
    const float* bias = (const float*)d_in[2];
    float* out = (float*)d_out;

    __nv_bfloat16 *aHi1, *aLo1, *aHi2, *aLo2, *aHi3, *aLo3, *wHi, *wLo;
    float *ll1, *ll2, *y1, *y2, *y3, *r2, *r1;
    cudaGetSymbolAddress((void**)&aHi1, g_aHi1);  cudaGetSymbolAddress((void**)&aLo1, g_aLo1);
    cudaGetSymbolAddress((void**)&aHi2, g_aHi2);  cudaGetSymbolAddress((void**)&aLo2, g_aLo2);
    cudaGetSymbolAddress((void**)&aHi3, g_aHi3);  cudaGetSymbolAddress((void**)&aLo3, g_aLo3);
    cudaGetSymbolAddress((void**)&wHi, g_wHi);    cudaGetSymbolAddress((void**)&wLo, g_wLo);
    cudaGetSymbolAddress((void**)&ll1, g_ll1);    cudaGetSymbolAddress((void**)&ll2, g_ll2);
    cudaGetSymbolAddress((void**)&y1, g_y1);      cudaGetSymbolAddress((void**)&y2, g_y2);
    cudaGetSymbolAddress((void**)&y3, g_y3);
    cudaGetSymbolAddress((void**)&r2, g_r2);      cudaGetSymbolAddress((void**)&r1, g_r1);

    cudaFuncSetAttribute(conv_mma, cudaFuncAttributeMaxDynamicSharedMemorySize, SMEM_TOTAL);

    wsplit_k<<<cdiv((long)9 * C4 * C4, 256), 256>>>(wgt, wHi, wLo);

    // level 1
    dwt_k<<<cdiv((long)NB * H1 * H1 * NC, 256), 256>>>(x, 1, 224, aHi1, aLo1, ll1, H1, H1);
    conv_mma<<<cdiv((long)NB * H1 * H1, BM), 256, SMEM_TOTAL>>>(aHi1, aLo1, wHi, wLo, y1, H1, H1);
    // level 2
    dwt_k<<<cdiv((long)NB * H2 * H2 * NC, 256), 256>>>(ll1, 0, H1, aHi2, aLo2, ll2, H2, H2);
    conv_mma<<<cdiv((long)NB * H2 * H2, BM), 256, SMEM_TOTAL>>>(aHi2, aLo2, wHi, wLo, y2, H2, H2);
    // level 3
    dwt_k<<<cdiv((long)NB * H3 * H3 * NC, 256), 256>>>(ll2, 0, H2, aHi3, aLo3, nullptr, H3, H3);
    conv_mma<<<cdiv((long)NB * H3 * H3, BM), 256, SMEM_TOTAL>>>(aHi3, aLo3, wHi, wLo, y3, H3, H3);

    // reconstruction
    idwt_k<<<cdiv((long)NB * H3 * H3 * NC, 256), 256>>>(y3, nullptr, r2, H3, H3, 0, nullptr);
    idwt_k<<<cdiv((long)NB * H2 * H2 * NC, 256), 256>>>(y2, r2, r1, H2, H2, 0, nullptr);
    idwt_k<<<cdiv((long)NB * H1 * H1 * NC, 256), 256>>>(y1, r1, out, H1, H1, 1, bias);
}